// round 5
// baseline (speedup 1.0000x reference)
#include <cuda_runtime.h>
#include <cuda_bf16.h>
#include <cstdint>

// ---------------------------------------------------------------------------
// loss2, 2 launches:
//   1) normalize -> bf16
//   2) fused: bf16 mma.sync rowsum GEMM, packed-f32x2 degree-6 exp epilogue;
//      last-of-split CTA recomputes in-block cosines (fp32 dots over the same
//      bf16 data) + per-row loss terms; last CTA overall reduces + writes out.
//      Arrival counters self-reset for graph replay.
//   Lean mainloop (no harvest), 2 CTAs/SM via halved accumulators + NSPLIT=8.
// ---------------------------------------------------------------------------

#define C_DIM 128
#define BLK 5
#define MAX_T 4096
#define TM 128
#define TN 128
#define NSPLIT 8

__device__ __align__(16) __nv_bfloat16 g_xbf[MAX_T * C_DIM];  // zero-init: rows>=T are 0
__device__ float g_part[NSPLIT][MAX_T];
__device__ float g_xterm[64];
__device__ int   g_cnt_x[64];          // zero-init; self-resetting
__device__ int   g_cnt_all;            // zero-init; self-resetting

// smem: A tile 32KB @0, B double buffer 2x32KB @32768  (96KB -> 2 CTAs/SM)
#define OFF_A 0
#define OFF_B 32768
#define SMEM_DYN 98304

// ---------------- helpers ----------------
__device__ __forceinline__ uint32_t smem_u32(const void* p) {
    uint32_t a;
    asm("{ .reg .u64 t; cvta.to.shared.u64 t, %1; cvt.u32.u64 %0, t; }" : "=r"(a) : "l"(p));
    return a;
}

__device__ __forceinline__ void cp_async16(uint32_t dst, const void* src) {
    asm volatile("cp.async.cg.shared.global [%0], [%1], 16;"
                 :: "r"(dst), "l"(__cvta_generic_to_global(src)));
}
#define CP_COMMIT()  asm volatile("cp.async.commit_group;" ::: "memory")
#define CP_WAIT(n)   asm volatile("cp.async.wait_group %0;" :: "n"(n) : "memory")

__device__ __forceinline__ void ldmatrix_x4(uint32_t* r, uint32_t addr) {
    asm volatile("ldmatrix.sync.aligned.m8n8.x4.shared.b16 {%0,%1,%2,%3}, [%4];"
                 : "=r"(r[0]), "=r"(r[1]), "=r"(r[2]), "=r"(r[3]) : "r"(addr));
}

__device__ __forceinline__ void mma_bf16(float* c, const uint32_t* a, const uint32_t* b) {
    asm volatile(
        "mma.sync.aligned.m16n8k16.row.col.f32.bf16.bf16.f32 "
        "{%0,%1,%2,%3}, {%4,%5,%6,%7}, {%8,%9}, {%0,%1,%2,%3};"
        : "+f"(c[0]), "+f"(c[1]), "+f"(c[2]), "+f"(c[3])
        : "r"(a[0]), "r"(a[1]), "r"(a[2]), "r"(a[3]), "r"(b[0]), "r"(b[1]));
}

// ---------------- fp32x2 packed math ----------------
__device__ __forceinline__ unsigned long long pk2(float lo, float hi) {
    unsigned long long r;
    asm("mov.b64 %0, {%1, %2};" : "=l"(r) : "f"(lo), "f"(hi));
    return r;
}
__device__ __forceinline__ float2 up2(unsigned long long v) {
    float2 r;
    asm("mov.b64 {%0, %1}, %2;" : "=f"(r.x), "=f"(r.y) : "l"(v));
    return r;
}
__device__ __forceinline__ unsigned long long fma2(unsigned long long a,
                                                   unsigned long long b,
                                                   unsigned long long c) {
    unsigned long long d;
    asm("fma.rn.f32x2 %0, %1, %2, %3;" : "=l"(d) : "l"(a), "l"(b), "l"(c));
    return d;
}
__device__ __forceinline__ unsigned long long add2(unsigned long long a,
                                                   unsigned long long b) {
    unsigned long long d;
    asm("add.rn.f32x2 %0, %1, %2;" : "=l"(d) : "l"(a), "l"(b));
    return d;
}
// exp(c) for |c| <= ~1.05, degree-6 Taylor; exp_pk(0) == 1.0 exactly.
__device__ __forceinline__ unsigned long long exp_pk(unsigned long long c) {
    unsigned long long p = pk2(1.3888889e-3f, 1.3888889e-3f);   // 1/6!
    p = fma2(p, c, pk2(8.3333333e-3f, 8.3333333e-3f));          // 1/5!
    p = fma2(p, c, pk2(4.1666667e-2f, 4.1666667e-2f));          // 1/4!
    p = fma2(p, c, pk2(1.6666667e-1f, 1.6666667e-1f));          // 1/3!
    p = fma2(p, c, pk2(0.5f, 0.5f));
    p = fma2(p, c, pk2(1.0f, 1.0f));
    p = fma2(p, c, pk2(1.0f, 1.0f));
    return p;
}

// tile smem layout: row-major 128 rows x 256B, 16B chunks XOR-swizzled by (row&7)
__device__ __forceinline__ void copy_tile_async(uint32_t dstb, int grow0, int tid) {
    #pragma unroll
    for (int l = 0; l < 8; l++) {
        int idx = tid + l * 256;               // 0..2047
        int row = idx >> 4;
        int ch  = idx & 15;
        cp_async16(dstb + row * 256 + ((ch ^ (row & 7)) << 4),
                   &g_xbf[(grow0 + row) * C_DIM + ch * 8]);
    }
}

// ---------------- kernels ----------------
__global__ void normalize_kernel(const float* __restrict__ x, int T) {
    int row = blockIdx.x;
    int t = threadIdx.x;                       // 128
    float v = x[row * C_DIM + t];
    float s = v * v;
    #pragma unroll
    for (int o = 16; o > 0; o >>= 1) s += __shfl_xor_sync(0xffffffffu, s, o);
    __shared__ float ws[4];
    if ((t & 31) == 0) ws[t >> 5] = s;
    __syncthreads();
    float tot = ws[0] + ws[1] + ws[2] + ws[3];
    float inv = 1.0f / fmaxf(sqrtf(tot), 1e-8f);
    g_xbf[row * C_DIM + t] = __float2bfloat16(v * inv);
}

__global__ void __launch_bounds__(256, 2) rowsum_fused(
    int T, int ntN, int ntM, float rscale, int Bnum,
    const int* __restrict__ kuai2, float* __restrict__ out)
{
    extern __shared__ char smem[];
    const uint32_t sb = smem_u32(smem);
    const int tid  = threadIdx.x;
    const int wid  = tid >> 5;
    const int lane = tid & 31;

    const int i0  = blockIdx.x * TM;
    const int tpc = (ntN + NSPLIT - 1) / NSPLIT;
    const int jt0 = blockIdx.y * tpc;
    const int nt  = min(tpc, ntN - jt0);

    if (nt > 0) {
        copy_tile_async(sb + OFF_A, i0, tid);
        CP_COMMIT();
        copy_tile_async(sb + OFF_B, jt0 * TN, tid);
        CP_COMMIT();

        const int mh = wid >> 2;               // M half (0/1)
        const int nq = wid & 3;                // N quarter (0..3)
        const int mrow = mh * 64;
        const int jw   = nq * 32;
        const int s7   = lane & 7;

        const int ro_a = (lane & 7) + ((lane >> 3) & 1) * 8;
        const int cg_a = (lane >> 4);
        const int ro_b = (lane & 7) + ((lane >> 4) & 1) * 8;
        const int cg_b = (lane >> 3) & 1;

        uint32_t a_addr[4];
        #pragma unroll
        for (int mi = 0; mi < 4; mi++)
            a_addr[mi] = sb + OFF_A + (mrow + mi * 16 + ro_a) * 256;

        // packed per-row accumulators: acc[mi*2+h] covers row mrow+mi*16+(lane>>2)+8h
        unsigned long long acc[8];
        #pragma unroll
        for (int q = 0; q < 8; q++) acc[q] = 0ull;
        int padtot = 0;

        for (int t = 0; t < nt; t++) {
            if (t + 1 < nt) {
                copy_tile_async(sb + OFF_B + ((t + 1) & 1) * 32768, (jt0 + t + 1) * TN, tid);
                CP_COMMIT();
                CP_WAIT(1);
            } else {
                CP_WAIT(0);
            }
            __syncthreads();

            const uint32_t bb = sb + OFF_B + (t & 1) * 32768;

            // two 16-column halves -> c[4][2][4] (32 regs) instead of 64
            #pragma unroll
            for (int h = 0; h < 2; h++) {
                const uint32_t b_base = bb + (jw + h * 16 + ro_b) * 256;
                float c[4][2][4];
                #pragma unroll
                for (int mi = 0; mi < 4; mi++)
                    #pragma unroll
                    for (int ni = 0; ni < 2; ni++)
                        #pragma unroll
                        for (int q = 0; q < 4; q++) c[mi][ni][q] = 0.f;

                #pragma unroll
                for (int ks = 0; ks < 8; ks++) {
                    const uint32_t chA = (uint32_t)(((ks * 2 + cg_a) ^ s7) << 4);
                    const uint32_t chB = (uint32_t)(((ks * 2 + cg_b) ^ s7) << 4);
                    uint32_t a[4][4], b[4];
                    #pragma unroll
                    for (int mi = 0; mi < 4; mi++) ldmatrix_x4(a[mi], a_addr[mi] + chA);
                    ldmatrix_x4(b, b_base + chB);
                    #pragma unroll
                    for (int mi = 0; mi < 4; mi++)
                        #pragma unroll
                        for (int ni = 0; ni < 2; ni++)
                            mma_bf16(c[mi][ni], a[mi], &b[ni * 2]);
                }

                #pragma unroll
                for (int mi = 0; mi < 4; mi++)
                    #pragma unroll
                    for (int ni = 0; ni < 2; ni++) {
                        acc[mi * 2]     = add2(acc[mi * 2],
                                               exp_pk(pk2(c[mi][ni][0], c[mi][ni][1])));
                        acc[mi * 2 + 1] = add2(acc[mi * 2 + 1],
                                               exp_pk(pk2(c[mi][ni][2], c[mi][ni][3])));
                    }
            }

            // padded (j >= T) columns contributed exactly 1.0 each
            const int j0 = (jt0 + t) * TN;
            if (j0 + TN > T) {
                #pragma unroll
                for (int h = 0; h < 2; h++)
                    #pragma unroll
                    for (int ni = 0; ni < 2; ni++) {
                        int col = j0 + jw + h * 16 + ni * 8 + 2 * (lane & 3);
                        padtot += (col >= T) + (col + 1 >= T);
                    }
            }
            __syncthreads();
        }

        float rowacc[8];
        #pragma unroll
        for (int q = 0; q < 8; q++) {
            float2 u = up2(acc[q]);
            rowacc[q] = (u.x + u.y) - (float)padtot;
        }
        #pragma unroll
        for (int q = 0; q < 8; q++) {
            rowacc[q] += __shfl_xor_sync(0xffffffffu, rowacc[q], 1);
            rowacc[q] += __shfl_xor_sync(0xffffffffu, rowacc[q], 2);
        }
        float* red = (float*)smem;             // reuse A region: red[4][128]
        if ((lane & 3) == 0) {
            int r = lane >> 2;
            #pragma unroll
            for (int mi = 0; mi < 4; mi++) {
                red[nq * 128 + mrow + mi * 16 + r]     = rowacc[mi * 2];
                red[nq * 128 + mrow + mi * 16 + r + 8] = rowacc[mi * 2 + 1];
            }
        }
        __syncthreads();
        if (tid < TM) {
            int gi = i0 + tid;
            if (gi < T)
                g_part[blockIdx.y][gi] =
                    red[tid] + red[128 + tid] + red[256 + tid] + red[384 + tid];
        }
    } else {
        if (tid < TM && i0 + tid < T) g_part[blockIdx.y][i0 + tid] = 0.f;
    }

    // ---- arrival: last of the NSPLIT CTAs for this x computes loss terms ----
    __threadfence();
    __shared__ int s_last, s_fin;
    if (tid == 0) {
        s_fin = 0;
        int old = atomicAdd(&g_cnt_x[blockIdx.x], 1);
        s_last = (old == NSPLIT - 1);
        if (s_last) g_cnt_x[blockIdx.x] = 0;   // reset for next replay
    }
    __syncthreads();
    if (!s_last) return;
    __threadfence();

    float term = 0.f;
    {
        int row = i0 + tid;
        if (tid < TM && row < T) {
            int bs = (row / BLK) * BLK;
            int me = row - bs;
            // in-block cosines: fp32 dots over the SAME bf16 data the GEMM used
            const __nv_bfloat162* xr = (const __nv_bfloat162*)&g_xbf[row * C_DIM];
            const __nv_bfloat162* x0 = (const __nv_bfloat162*)&g_xbf[bs * C_DIM];
            float cb[BLK] = {0.f, 0.f, 0.f, 0.f, 0.f};
            #pragma unroll 8
            for (int kq = 0; kq < C_DIM / 2; kq++) {
                float2 u = __bfloat1622float2(xr[kq]);
                #pragma unroll
                for (int m = 0; m < BLK; m++) {
                    float2 v = __bfloat1622float2(x0[m * (C_DIM / 2) + kq]);
                    cb[m] = fmaf(u.x, v.x, fmaf(u.y, v.y, cb[m]));
                }
            }
            float es[BLK], bsum = 0.f;
            #pragma unroll
            for (int m = 0; m < BLK; m++) { es[m] = expf(cb[m]); bsum += es[m]; }
            float rs = 0.f;
            #pragma unroll
            for (int s = 0; s < NSPLIT; s++) rs += g_part[s][row];
            float negA = rscale * (rs - bsum);
            #pragma unroll
            for (int m = 0; m < BLK; m++)
                if (m != me) term += logf(es[m] + negA) - cb[m];
        }
    }
    #pragma unroll
    for (int o = 16; o > 0; o >>= 1) term += __shfl_xor_sync(0xffffffffu, term, o);
    __shared__ float ws2[8];
    if (lane == 0) ws2[wid] = term;
    __syncthreads();
    if (tid == 0) {
        float s = 0.f;
        #pragma unroll
        for (int k = 0; k < 8; k++) s += ws2[k];
        g_xterm[blockIdx.x] = s;
        __threadfence();
        int o = atomicAdd(&g_cnt_all, 1);
        s_fin = (o == ntM - 1);
        if (s_fin) g_cnt_all = 0;              // reset for next replay
    }
    __syncthreads();
    if (s_fin && tid < 32) {
        __threadfence();
        double s = (tid < ntM) ? (double)g_xterm[tid] : 0.0;
        #pragma unroll
        for (int o = 16; o > 0; o >>= 1) s += __shfl_xor_sync(0xffffffffu, s, o);
        if (tid == 0) {
            int k2 = *kuai2;
            out[0] = (float)(s / ((double)Bnum * (double)k2 * (double)(k2 - 1)));
        }
    }
}

// ---------------- launch ----------------
extern "C" void kernel_launch(void* const* d_in, const int* in_sizes, int n_in,
                              void* d_out, int out_size) {
    const float* x     = (const float*)d_in[0];
    const int*   kuai2 = (const int*)d_in[1];

    int T = in_sizes[0] / C_DIM;
    int B = T / BLK;
    float r = (float)(2 * B - 2) / (float)(T - BLK);
    int ntM = (T + TM - 1) / TM;
    int ntN = (T + TN - 1) / TN;

    cudaFuncSetAttribute(rowsum_fused, cudaFuncAttributeMaxDynamicSharedMemorySize, SMEM_DYN);

    normalize_kernel<<<T, C_DIM>>>(x, T);
    dim3 grid(ntM, NSPLIT);
    rowsum_fused<<<grid, 256, SMEM_DYN>>>(T, ntN, ntM, r, B, kuai2, (float*)d_out);
}

// round 6
// speedup vs baseline: 1.3010x; 1.3010x over previous
#include <cuda_runtime.h>
#include <cuda_bf16.h>
#include <cstdint>

// ---------------------------------------------------------------------------
// loss2, 2 launches:
//   1) normalize -> bf16
//   2) fused: bf16 mma.sync rowsum GEMM (lean mainloop, R3 shape) with
//      packed-f32x2 degree-6 exp epilogue; last-of-split CTA recomputes
//      in-block cosines (fp32 dots over the same bf16 data) + per-row loss
//      terms; last CTA overall reduces + writes out. Counters self-reset.
// ---------------------------------------------------------------------------

#define C_DIM 128
#define BLK 5
#define MAX_T 4096
#define TM 128
#define TN 128
#define NSPLIT 4

__device__ __align__(16) __nv_bfloat16 g_xbf[MAX_T * C_DIM];  // zero-init: rows>=T are 0
__device__ float g_part[NSPLIT][MAX_T];
__device__ float g_xterm[64];
__device__ int   g_cnt_x[64];          // zero-init; self-resetting
__device__ int   g_cnt_all;            // zero-init; self-resetting

// smem: A tile 32KB @0, B double buffer 2x32KB @32768
#define OFF_A 0
#define OFF_B 32768
#define SMEM_DYN 98304

// ---------------- helpers ----------------
__device__ __forceinline__ uint32_t smem_u32(const void* p) {
    uint32_t a;
    asm("{ .reg .u64 t; cvta.to.shared.u64 t, %1; cvt.u32.u64 %0, t; }" : "=r"(a) : "l"(p));
    return a;
}

__device__ __forceinline__ void cp_async16(uint32_t dst, const void* src) {
    asm volatile("cp.async.cg.shared.global [%0], [%1], 16;"
                 :: "r"(dst), "l"(__cvta_generic_to_global(src)));
}
#define CP_COMMIT()  asm volatile("cp.async.commit_group;" ::: "memory")
#define CP_WAIT(n)   asm volatile("cp.async.wait_group %0;" :: "n"(n) : "memory")

__device__ __forceinline__ void ldmatrix_x4(uint32_t* r, uint32_t addr) {
    asm volatile("ldmatrix.sync.aligned.m8n8.x4.shared.b16 {%0,%1,%2,%3}, [%4];"
                 : "=r"(r[0]), "=r"(r[1]), "=r"(r[2]), "=r"(r[3]) : "r"(addr));
}

__device__ __forceinline__ void mma_bf16(float* c, const uint32_t* a, const uint32_t* b) {
    asm volatile(
        "mma.sync.aligned.m16n8k16.row.col.f32.bf16.bf16.f32 "
        "{%0,%1,%2,%3}, {%4,%5,%6,%7}, {%8,%9}, {%0,%1,%2,%3};"
        : "+f"(c[0]), "+f"(c[1]), "+f"(c[2]), "+f"(c[3])
        : "r"(a[0]), "r"(a[1]), "r"(a[2]), "r"(a[3]), "r"(b[0]), "r"(b[1]));
}

// ---------------- fp32x2 packed math ----------------
__device__ __forceinline__ unsigned long long pk2(float lo, float hi) {
    unsigned long long r;
    asm("mov.b64 %0, {%1, %2};" : "=l"(r) : "f"(lo), "f"(hi));
    return r;
}
__device__ __forceinline__ float2 up2(unsigned long long v) {
    float2 r;
    asm("mov.b64 {%0, %1}, %2;" : "=f"(r.x), "=f"(r.y) : "l"(v));
    return r;
}
__device__ __forceinline__ unsigned long long fma2(unsigned long long a,
                                                   unsigned long long b,
                                                   unsigned long long c) {
    unsigned long long d;
    asm("fma.rn.f32x2 %0, %1, %2, %3;" : "=l"(d) : "l"(a), "l"(b), "l"(c));
    return d;
}
__device__ __forceinline__ unsigned long long add2(unsigned long long a,
                                                   unsigned long long b) {
    unsigned long long d;
    asm("add.rn.f32x2 %0, %1, %2;" : "=l"(d) : "l"(a), "l"(b));
    return d;
}
// exp(c) for |c| <= ~1.05, degree-6 Taylor; exp_pk(0) == 1.0 exactly.
__device__ __forceinline__ unsigned long long exp_pk(unsigned long long c) {
    unsigned long long p = pk2(1.3888889e-3f, 1.3888889e-3f);   // 1/6!
    p = fma2(p, c, pk2(8.3333333e-3f, 8.3333333e-3f));          // 1/5!
    p = fma2(p, c, pk2(4.1666667e-2f, 4.1666667e-2f));          // 1/4!
    p = fma2(p, c, pk2(1.6666667e-1f, 1.6666667e-1f));          // 1/3!
    p = fma2(p, c, pk2(0.5f, 0.5f));
    p = fma2(p, c, pk2(1.0f, 1.0f));
    p = fma2(p, c, pk2(1.0f, 1.0f));
    return p;
}

// tile smem layout: row-major 128 rows x 256B, 16B chunks XOR-swizzled by (row&7)
__device__ __forceinline__ void copy_tile_async(uint32_t dstb, int grow0, int tid) {
    #pragma unroll
    for (int l = 0; l < 8; l++) {
        int idx = tid + l * 256;               // 0..2047
        int row = idx >> 4;
        int ch  = idx & 15;
        cp_async16(dstb + row * 256 + ((ch ^ (row & 7)) << 4),
                   &g_xbf[(grow0 + row) * C_DIM + ch * 8]);
    }
}

// ---------------- kernels ----------------
__global__ void normalize_kernel(const float* __restrict__ x, int T) {
    int row = blockIdx.x;
    int t = threadIdx.x;                       // 128
    float v = x[row * C_DIM + t];
    float s = v * v;
    #pragma unroll
    for (int o = 16; o > 0; o >>= 1) s += __shfl_xor_sync(0xffffffffu, s, o);
    __shared__ float ws[4];
    if ((t & 31) == 0) ws[t >> 5] = s;
    __syncthreads();
    float tot = ws[0] + ws[1] + ws[2] + ws[3];
    float inv = 1.0f / fmaxf(sqrtf(tot), 1e-8f);
    g_xbf[row * C_DIM + t] = __float2bfloat16(v * inv);
}

__global__ __launch_bounds__(256) void rowsum_fused(
    int T, int ntN, int ntM, float rscale, int Bnum,
    const int* __restrict__ kuai2, float* __restrict__ out)
{
    extern __shared__ char smem[];
    const uint32_t sb = smem_u32(smem);
    const int tid  = threadIdx.x;
    const int wid  = tid >> 5;
    const int lane = tid & 31;

    const int i0  = blockIdx.x * TM;
    const int tpc = (ntN + NSPLIT - 1) / NSPLIT;
    const int jt0 = blockIdx.y * tpc;
    const int nt  = min(tpc, ntN - jt0);

    if (nt > 0) {
        // pipeline: group0 = A, group1 = B(0)
        copy_tile_async(sb + OFF_A, i0, tid);
        CP_COMMIT();
        copy_tile_async(sb + OFF_B, jt0 * TN, tid);
        CP_COMMIT();

        const int mh = wid >> 2;               // M half (0/1)
        const int nq = wid & 3;                // N quarter (0..3)
        const int mrow = mh * 64;
        const int jw   = nq * 32;
        const int s7   = lane & 7;

        const int ro_a = (lane & 7) + ((lane >> 3) & 1) * 8;
        const int cg_a = (lane >> 4);
        const int ro_b = (lane & 7) + ((lane >> 4) & 1) * 8;
        const int cg_b = (lane >> 3) & 1;

        uint32_t a_addr[4], b_base[2];
        #pragma unroll
        for (int mi = 0; mi < 4; mi++)
            a_addr[mi] = sb + OFF_A + (mrow + mi * 16 + ro_a) * 256;
        #pragma unroll
        for (int p = 0; p < 2; p++)
            b_base[p] = (jw + p * 16 + ro_b) * 256;

        // packed per-row accumulators: acc[mi*2+h] covers row mrow+mi*16+(lane>>2)+8h
        unsigned long long acc[8];
        #pragma unroll
        for (int q = 0; q < 8; q++) acc[q] = 0ull;
        int padtot = 0;

        for (int t = 0; t < nt; t++) {
            if (t + 1 < nt) {
                copy_tile_async(sb + OFF_B + ((t + 1) & 1) * 32768, (jt0 + t + 1) * TN, tid);
                CP_COMMIT();
                CP_WAIT(1);
            } else {
                CP_WAIT(0);
            }
            __syncthreads();

            const uint32_t bb = sb + OFF_B + (t & 1) * 32768;

            float c[4][4][4];
            #pragma unroll
            for (int mi = 0; mi < 4; mi++)
                #pragma unroll
                for (int ni = 0; ni < 4; ni++)
                    #pragma unroll
                    for (int q = 0; q < 4; q++) c[mi][ni][q] = 0.f;

            #pragma unroll
            for (int ks = 0; ks < 8; ks++) {
                const uint32_t chA = (uint32_t)(((ks * 2 + cg_a) ^ s7) << 4);
                const uint32_t chB = (uint32_t)(((ks * 2 + cg_b) ^ s7) << 4);
                uint32_t a[4][4], b[2][4];
                #pragma unroll
                for (int mi = 0; mi < 4; mi++) ldmatrix_x4(a[mi], a_addr[mi] + chA);
                #pragma unroll
                for (int p = 0; p < 2; p++)    ldmatrix_x4(b[p], bb + b_base[p] + chB);
                #pragma unroll
                for (int mi = 0; mi < 4; mi++)
                    #pragma unroll
                    for (int ni = 0; ni < 4; ni++)
                        mma_bf16(c[mi][ni], a[mi], &b[ni >> 1][(ni & 1) * 2]);
            }

            // epilogue: packed exp + packed per-row accumulate
            #pragma unroll
            for (int mi = 0; mi < 4; mi++)
                #pragma unroll
                for (int ni = 0; ni < 4; ni++) {
                    acc[mi * 2]     = add2(acc[mi * 2],
                                           exp_pk(pk2(c[mi][ni][0], c[mi][ni][1])));
                    acc[mi * 2 + 1] = add2(acc[mi * 2 + 1],
                                           exp_pk(pk2(c[mi][ni][2], c[mi][ni][3])));
                }

            // padded (j >= T) columns contributed exactly 1.0 each
            const int j0 = (jt0 + t) * TN;
            if (j0 + TN > T) {
                #pragma unroll
                for (int ni = 0; ni < 4; ni++) {
                    int col = j0 + jw + ni * 8 + 2 * (lane & 3);
                    padtot += (col >= T) + (col + 1 >= T);
                }
            }
            __syncthreads();
        }

        float rowacc[8];
        #pragma unroll
        for (int q = 0; q < 8; q++) {
            float2 u = up2(acc[q]);
            rowacc[q] = (u.x + u.y) - (float)padtot;
        }
        // reduce over the 4 lanes sharing each row
        #pragma unroll
        for (int q = 0; q < 8; q++) {
            rowacc[q] += __shfl_xor_sync(0xffffffffu, rowacc[q], 1);
            rowacc[q] += __shfl_xor_sync(0xffffffffu, rowacc[q], 2);
        }
        float* red = (float*)smem;             // reuse A region: red[4][128]
        if ((lane & 3) == 0) {
            int r = lane >> 2;
            #pragma unroll
            for (int mi = 0; mi < 4; mi++) {
                red[nq * 128 + mrow + mi * 16 + r]     = rowacc[mi * 2];
                red[nq * 128 + mrow + mi * 16 + r + 8] = rowacc[mi * 2 + 1];
            }
        }
        __syncthreads();
        if (tid < TM) {
            int gi = i0 + tid;
            if (gi < T)
                g_part[blockIdx.y][gi] =
                    red[tid] + red[128 + tid] + red[256 + tid] + red[384 + tid];
        }
    } else {
        if (tid < TM && i0 + tid < T) g_part[blockIdx.y][i0 + tid] = 0.f;
    }

    // ---- arrival: last of the NSPLIT CTAs for this x computes loss terms ----
    __threadfence();
    __shared__ int s_last, s_fin;
    if (tid == 0) {
        s_fin = 0;
        int old = atomicAdd(&g_cnt_x[blockIdx.x], 1);
        s_last = (old == NSPLIT - 1);
        if (s_last) g_cnt_x[blockIdx.x] = 0;   // reset for next replay
    }
    __syncthreads();
    if (!s_last) return;
    __threadfence();

    float term = 0.f;
    {
        int row = i0 + tid;
        if (tid < TM && row < T) {
            int bs = (row / BLK) * BLK;
            int me = row - bs;
            // in-block cosines: fp32 dots over the SAME bf16 data the GEMM used
            const __nv_bfloat162* xr = (const __nv_bfloat162*)&g_xbf[row * C_DIM];
            const __nv_bfloat162* x0 = (const __nv_bfloat162*)&g_xbf[bs * C_DIM];
            float cb[BLK] = {0.f, 0.f, 0.f, 0.f, 0.f};
            #pragma unroll 8
            for (int kq = 0; kq < C_DIM / 2; kq++) {
                float2 u = __bfloat1622float2(xr[kq]);
                #pragma unroll
                for (int m = 0; m < BLK; m++) {
                    float2 v = __bfloat1622float2(x0[m * (C_DIM / 2) + kq]);
                    cb[m] = fmaf(u.x, v.x, fmaf(u.y, v.y, cb[m]));
                }
            }
            float es[BLK], bsum = 0.f;
            #pragma unroll
            for (int m = 0; m < BLK; m++) { es[m] = expf(cb[m]); bsum += es[m]; }
            float rs = 0.f;
            #pragma unroll
            for (int s = 0; s < NSPLIT; s++) rs += g_part[s][row];
            float negA = rscale * (rs - bsum);
            #pragma unroll
            for (int m = 0; m < BLK; m++)
                if (m != me) term += logf(es[m] + negA) - cb[m];
        }
    }
    #pragma unroll
    for (int o = 16; o > 0; o >>= 1) term += __shfl_xor_sync(0xffffffffu, term, o);
    __shared__ float ws2[8];
    if (lane == 0) ws2[wid] = term;
    __syncthreads();
    if (tid == 0) {
        float s = 0.f;
        #pragma unroll
        for (int k = 0; k < 8; k++) s += ws2[k];
        g_xterm[blockIdx.x] = s;
        __threadfence();
        int o = atomicAdd(&g_cnt_all, 1);
        s_fin = (o == ntM - 1);
        if (s_fin) g_cnt_all = 0;              // reset for next replay
    }
    __syncthreads();
    if (s_fin && tid < 32) {
        __threadfence();
        double s = (tid < ntM) ? (double)g_xterm[tid] : 0.0;
        #pragma unroll
        for (int o = 16; o > 0; o >>= 1) s += __shfl_xor_sync(0xffffffffu, s, o);
        if (tid == 0) {
            int k2 = *kuai2;
            out[0] = (float)(s / ((double)Bnum * (double)k2 * (double)(k2 - 1)));
        }
    }
}

// ---------------- launch ----------------
extern "C" void kernel_launch(void* const* d_in, const int* in_sizes, int n_in,
                              void* d_out, int out_size) {
    const float* x     = (const float*)d_in[0];
    const int*   kuai2 = (const int*)d_in[1];

    int T = in_sizes[0] / C_DIM;
    int B = T / BLK;
    float r = (float)(2 * B - 2) / (float)(T - BLK);
    int ntM = (T + TM - 1) / TM;
    int ntN = (T + TN - 1) / TN;

    cudaFuncSetAttribute(rowsum_fused, cudaFuncAttributeMaxDynamicSharedMemorySize, SMEM_DYN);

    normalize_kernel<<<T, C_DIM>>>(x, T);
    dim3 grid(ntM, NSPLIT);
    rowsum_fused<<<grid, 256, SMEM_DYN>>>(T, ntN, ntM, r, B, kuai2, (float*)d_out);
}

// round 7
// speedup vs baseline: 1.5337x; 1.1789x over previous
#include <cuda_runtime.h>
#include <cuda_bf16.h>
#include <cstdint>

// ---------------------------------------------------------------------------
// loss2, 3 launches:
//   1) normalize -> bf16
//   2) rowsum GEMM: bf16 mma.sync, 512 threads (16 warps, 32x32 warp tiles),
//      packed-f32x2 degree-6 exp epilogue, NSPLIT column splits -> g_part
//   3) pairs+finalize (counter-fused): warp-per-block in-block cosines (fp32
//      dots over the same bf16 data), loss terms, final reduce -> out
// ---------------------------------------------------------------------------

#define C_DIM 128
#define BLK 5
#define MAX_T 4096
#define TM 128
#define TN 128
#define NSPLIT 4
#define NTHR 512

__device__ __align__(16) __nv_bfloat16 g_xbf[MAX_T * C_DIM];  // zero-init: rows>=T are 0
__device__ float g_part[NSPLIT][MAX_T];
__device__ float g_pairpart[128];
__device__ int   g_cnt;                // zero-init; self-resetting

// smem: A tile 32KB @0, B double buffer 2x32KB @32768
#define OFF_A 0
#define OFF_B 32768
#define SMEM_DYN 98304

// ---------------- helpers ----------------
__device__ __forceinline__ uint32_t smem_u32(const void* p) {
    uint32_t a;
    asm("{ .reg .u64 t; cvta.to.shared.u64 t, %1; cvt.u32.u64 %0, t; }" : "=r"(a) : "l"(p));
    return a;
}

__device__ __forceinline__ void cp_async16(uint32_t dst, const void* src) {
    asm volatile("cp.async.cg.shared.global [%0], [%1], 16;"
                 :: "r"(dst), "l"(__cvta_generic_to_global(src)));
}
#define CP_COMMIT()  asm volatile("cp.async.commit_group;" ::: "memory")
#define CP_WAIT(n)   asm volatile("cp.async.wait_group %0;" :: "n"(n) : "memory")

__device__ __forceinline__ void ldmatrix_x4(uint32_t* r, uint32_t addr) {
    asm volatile("ldmatrix.sync.aligned.m8n8.x4.shared.b16 {%0,%1,%2,%3}, [%4];"
                 : "=r"(r[0]), "=r"(r[1]), "=r"(r[2]), "=r"(r[3]) : "r"(addr));
}

__device__ __forceinline__ void mma_bf16(float* c, const uint32_t* a, const uint32_t* b) {
    asm volatile(
        "mma.sync.aligned.m16n8k16.row.col.f32.bf16.bf16.f32 "
        "{%0,%1,%2,%3}, {%4,%5,%6,%7}, {%8,%9}, {%0,%1,%2,%3};"
        : "+f"(c[0]), "+f"(c[1]), "+f"(c[2]), "+f"(c[3])
        : "r"(a[0]), "r"(a[1]), "r"(a[2]), "r"(a[3]), "r"(b[0]), "r"(b[1]));
}

// ---------------- fp32x2 packed math ----------------
__device__ __forceinline__ unsigned long long pk2(float lo, float hi) {
    unsigned long long r;
    asm("mov.b64 %0, {%1, %2};" : "=l"(r) : "f"(lo), "f"(hi));
    return r;
}
__device__ __forceinline__ float2 up2(unsigned long long v) {
    float2 r;
    asm("mov.b64 {%0, %1}, %2;" : "=f"(r.x), "=f"(r.y) : "l"(v));
    return r;
}
__device__ __forceinline__ unsigned long long fma2(unsigned long long a,
                                                   unsigned long long b,
                                                   unsigned long long c) {
    unsigned long long d;
    asm("fma.rn.f32x2 %0, %1, %2, %3;" : "=l"(d) : "l"(a), "l"(b), "l"(c));
    return d;
}
__device__ __forceinline__ unsigned long long add2(unsigned long long a,
                                                   unsigned long long b) {
    unsigned long long d;
    asm("add.rn.f32x2 %0, %1, %2;" : "=l"(d) : "l"(a), "l"(b));
    return d;
}
// exp(c) for |c| <= ~1.05, degree-6 Taylor; exp_pk(0) == 1.0 exactly.
__device__ __forceinline__ unsigned long long exp_pk(unsigned long long c) {
    unsigned long long p = pk2(1.3888889e-3f, 1.3888889e-3f);   // 1/6!
    p = fma2(p, c, pk2(8.3333333e-3f, 8.3333333e-3f));          // 1/5!
    p = fma2(p, c, pk2(4.1666667e-2f, 4.1666667e-2f));          // 1/4!
    p = fma2(p, c, pk2(1.6666667e-1f, 1.6666667e-1f));          // 1/3!
    p = fma2(p, c, pk2(0.5f, 0.5f));
    p = fma2(p, c, pk2(1.0f, 1.0f));
    p = fma2(p, c, pk2(1.0f, 1.0f));
    return p;
}

// tile smem layout: row-major 128 rows x 256B, 16B chunks XOR-swizzled by (row&7)
__device__ __forceinline__ void copy_tile_async(uint32_t dstb, int grow0, int tid) {
    #pragma unroll
    for (int l = 0; l < 4; l++) {
        int idx = tid + l * NTHR;              // 0..2047
        int row = idx >> 4;
        int ch  = idx & 15;
        cp_async16(dstb + row * 256 + ((ch ^ (row & 7)) << 4),
                   &g_xbf[(grow0 + row) * C_DIM + ch * 8]);
    }
}

// ---------------- kernels ----------------
__global__ void normalize_kernel(const float* __restrict__ x, int T) {
    int row = blockIdx.x;
    int t = threadIdx.x;                       // 128
    float v = x[row * C_DIM + t];
    float s = v * v;
    #pragma unroll
    for (int o = 16; o > 0; o >>= 1) s += __shfl_xor_sync(0xffffffffu, s, o);
    __shared__ float ws[4];
    if ((t & 31) == 0) ws[t >> 5] = s;
    __syncthreads();
    float tot = ws[0] + ws[1] + ws[2] + ws[3];
    float inv = 1.0f / fmaxf(sqrtf(tot), 1e-8f);
    g_xbf[row * C_DIM + t] = __float2bfloat16(v * inv);
}

__global__ __launch_bounds__(NTHR) void rowsum_mma(int T, int ntN) {
    extern __shared__ char smem[];
    const uint32_t sb = smem_u32(smem);
    const int tid  = threadIdx.x;
    const int wid  = tid >> 5;                 // 0..15
    const int lane = tid & 31;

    const int i0  = blockIdx.x * TM;
    const int tpc = (ntN + NSPLIT - 1) / NSPLIT;
    const int jt0 = blockIdx.y * tpc;
    const int nt  = min(tpc, ntN - jt0);
    if (nt <= 0) {
        if (tid < TM && i0 + tid < T) g_part[blockIdx.y][i0 + tid] = 0.f;
        return;
    }

    copy_tile_async(sb + OFF_A, i0, tid);
    CP_COMMIT();
    copy_tile_async(sb + OFF_B, jt0 * TN, tid);
    CP_COMMIT();

    const int mq = wid >> 2;                   // M quarter (0..3): 32 rows
    const int nq = wid & 3;                    // N quarter (0..3): 32 cols
    const int mrow = mq * 32;
    const int jw   = nq * 32;
    const int s7   = lane & 7;

    const int ro_a = (lane & 7) + ((lane >> 3) & 1) * 8;
    const int cg_a = (lane >> 4);
    const int ro_b = (lane & 7) + ((lane >> 4) & 1) * 8;
    const int cg_b = (lane >> 3) & 1;

    uint32_t a_addr[2], b_base[2];
    #pragma unroll
    for (int mi = 0; mi < 2; mi++)
        a_addr[mi] = sb + OFF_A + (mrow + mi * 16 + ro_a) * 256;
    #pragma unroll
    for (int p = 0; p < 2; p++)
        b_base[p] = (jw + p * 16 + ro_b) * 256;

    // packed per-row accumulators: acc[mi*2+h] covers row mrow+mi*16+(lane>>2)+8h
    unsigned long long acc[4] = {0ull, 0ull, 0ull, 0ull};
    int padtot = 0;

    for (int t = 0; t < nt; t++) {
        if (t + 1 < nt) {
            copy_tile_async(sb + OFF_B + ((t + 1) & 1) * 32768, (jt0 + t + 1) * TN, tid);
            CP_COMMIT();
            CP_WAIT(1);
        } else {
            CP_WAIT(0);
        }
        __syncthreads();

        const uint32_t bb = sb + OFF_B + (t & 1) * 32768;

        float c[2][4][4];
        #pragma unroll
        for (int mi = 0; mi < 2; mi++)
            #pragma unroll
            for (int ni = 0; ni < 4; ni++)
                #pragma unroll
                for (int q = 0; q < 4; q++) c[mi][ni][q] = 0.f;

        #pragma unroll
        for (int ks = 0; ks < 8; ks++) {
            const uint32_t chA = (uint32_t)(((ks * 2 + cg_a) ^ s7) << 4);
            const uint32_t chB = (uint32_t)(((ks * 2 + cg_b) ^ s7) << 4);
            uint32_t a[2][4], b[2][4];
            #pragma unroll
            for (int mi = 0; mi < 2; mi++) ldmatrix_x4(a[mi], a_addr[mi] + chA);
            #pragma unroll
            for (int p = 0; p < 2; p++)    ldmatrix_x4(b[p], bb + b_base[p] + chB);
            #pragma unroll
            for (int mi = 0; mi < 2; mi++)
                #pragma unroll
                for (int ni = 0; ni < 4; ni++)
                    mma_bf16(c[mi][ni], a[mi], &b[ni >> 1][(ni & 1) * 2]);
        }

        // epilogue: packed exp + packed per-row accumulate
        #pragma unroll
        for (int mi = 0; mi < 2; mi++)
            #pragma unroll
            for (int ni = 0; ni < 4; ni++) {
                acc[mi * 2]     = add2(acc[mi * 2],
                                       exp_pk(pk2(c[mi][ni][0], c[mi][ni][1])));
                acc[mi * 2 + 1] = add2(acc[mi * 2 + 1],
                                       exp_pk(pk2(c[mi][ni][2], c[mi][ni][3])));
            }

        // padded (j >= T) columns contributed exactly 1.0 each
        const int j0 = (jt0 + t) * TN;
        if (j0 + TN > T) {
            #pragma unroll
            for (int ni = 0; ni < 4; ni++) {
                int col = j0 + jw + ni * 8 + 2 * (lane & 3);
                padtot += (col >= T) + (col + 1 >= T);
            }
        }
        __syncthreads();
    }

    float rowacc[4];
    #pragma unroll
    for (int q = 0; q < 4; q++) {
        float2 u = up2(acc[q]);
        rowacc[q] = (u.x + u.y) - (float)padtot;
    }
    // reduce over the 4 lanes sharing each row
    #pragma unroll
    for (int q = 0; q < 4; q++) {
        rowacc[q] += __shfl_xor_sync(0xffffffffu, rowacc[q], 1);
        rowacc[q] += __shfl_xor_sync(0xffffffffu, rowacc[q], 2);
    }
    float* red = (float*)smem;                 // reuse A region: red[4][128]
    if ((lane & 3) == 0) {
        int r = lane >> 2;
        #pragma unroll
        for (int mi = 0; mi < 2; mi++) {
            red[nq * 128 + mrow + mi * 16 + r]     = rowacc[mi * 2];
            red[nq * 128 + mrow + mi * 16 + r + 8] = rowacc[mi * 2 + 1];
        }
    }
    __syncthreads();
    if (tid < TM) {
        int gi = i0 + tid;
        if (gi < T)
            g_part[blockIdx.y][gi] =
                red[tid] + red[128 + tid] + red[256 + tid] + red[384 + tid];
    }
}

// warp-per-block: in-block cosines (fp32 dots over the same bf16 data) + loss
// terms; counter-fused final reduction writes out.
__global__ __launch_bounds__(256) void pairs_finalize(
    float rscale, int Bnum, int ncta, const int* __restrict__ kuai2,
    float* __restrict__ out)
{
    const int lane = threadIdx.x & 31;
    const int wid  = threadIdx.x >> 5;
    const int b    = blockIdx.x * 8 + wid;

    float warp_term = 0.f;
    if (b < Bnum) {
        // each lane holds 4 consecutive elements (lane*4) of each of the 5 rows
        float4 u[BLK];
        #pragma unroll
        for (int m = 0; m < BLK; m++) {
            const __nv_bfloat162* p =
                (const __nv_bfloat162*)&g_xbf[(b * BLK + m) * C_DIM + lane * 4];
            float2 lo = __bfloat1622float2(p[0]);
            float2 hi = __bfloat1622float2(p[1]);
            u[m] = make_float4(lo.x, lo.y, hi.x, hi.y);
        }
        float cm[BLK][BLK];
        #pragma unroll
        for (int i = 0; i < BLK; i++)
            #pragma unroll
            for (int j = i; j < BLK; j++) {
                float s = u[i].x * u[j].x + u[i].y * u[j].y
                        + u[i].z * u[j].z + u[i].w * u[j].w;
                #pragma unroll
                for (int o = 16; o > 0; o >>= 1) s += __shfl_xor_sync(0xffffffffu, s, o);
                cm[i][j] = s; cm[j][i] = s;
            }
        float term = 0.f;
        if (lane < BLK) {
            int i = lane;
            float es[BLK], bsum = 0.f;
            #pragma unroll
            for (int m = 0; m < BLK; m++) { es[m] = expf(cm[i][m]); bsum += es[m]; }
            int row = b * BLK + i;
            float rs = 0.f;
            #pragma unroll
            for (int s = 0; s < NSPLIT; s++) rs += g_part[s][row];
            float negA = rscale * (rs - bsum);
            #pragma unroll
            for (int m = 0; m < BLK; m++)
                if (m != i) term += logf(es[m] + negA) - cm[i][m];
        }
        #pragma unroll
        for (int o = 16; o > 0; o >>= 1) term += __shfl_xor_sync(0xffffffffu, term, o);
        warp_term = term;
    }

    __shared__ float ws[8];
    __shared__ int s_fin;
    if (lane == 0) ws[wid] = warp_term;
    __syncthreads();
    if (threadIdx.x == 0) {
        float s = 0.f;
        #pragma unroll
        for (int k = 0; k < 8; k++) s += ws[k];
        g_pairpart[blockIdx.x] = s;
        __threadfence();
        int o = atomicAdd(&g_cnt, 1);
        s_fin = (o == ncta - 1);
        if (s_fin) g_cnt = 0;                  // reset for next replay
    }
    __syncthreads();
    if (s_fin && threadIdx.x < 32) {
        __threadfence();
        double s = 0.0;
        for (int i = threadIdx.x; i < ncta; i += 32) s += (double)g_pairpart[i];
        #pragma unroll
        for (int o = 16; o > 0; o >>= 1) s += __shfl_xor_sync(0xffffffffu, s, o);
        if (threadIdx.x == 0) {
            int k2 = *kuai2;
            out[0] = (float)(s / ((double)Bnum * (double)k2 * (double)(k2 - 1)));
        }
    }
}

// ---------------- launch ----------------
extern "C" void kernel_launch(void* const* d_in, const int* in_sizes, int n_in,
                              void* d_out, int out_size) {
    const float* x     = (const float*)d_in[0];
    const int*   kuai2 = (const int*)d_in[1];

    int T = in_sizes[0] / C_DIM;
    int B = T / BLK;
    float r = (float)(2 * B - 2) / (float)(T - BLK);
    int ntM = (T + TM - 1) / TM;
    int ntN = (T + TN - 1) / TN;
    int ncta_pairs = (B + 7) / 8;

    cudaFuncSetAttribute(rowsum_mma, cudaFuncAttributeMaxDynamicSharedMemorySize, SMEM_DYN);

    normalize_kernel<<<T, C_DIM>>>(x, T);
    dim3 grid(ntM, NSPLIT);
    rowsum_mma<<<grid, NTHR, SMEM_DYN>>>(T, ntN);
    pairs_finalize<<<ncta_pairs, 256>>>(r, B, ncta_pairs, kuai2, (float*)d_out);
}

// round 8
// speedup vs baseline: 1.7462x; 1.1385x over previous
#include <cuda_runtime.h>
#include <cuda_bf16.h>
#include <cstdint>

// ---------------------------------------------------------------------------
// loss2, 3 launches:
//   1) normalize -> bf16 (warp per row) + zero g_rowsum
//   2) rowsum GEMM over UPPER-TRIANGLE tiles only (symmetry): bf16 mma.sync,
//      512 threads, 32x32 warp tiles, triple-buffered A+B stages (1 sync/tile),
//      packed-f32x2 degree-6 exp epilogue feeding BOTH row sums and (for
//      off-diagonal tiles) column sums via fp32 atomicAdd into g_rowsum.
//   3) pairs+finalize (counter-fused) -> out
// ---------------------------------------------------------------------------

#define C_DIM 128
#define BLK 5
#define MAX_T 4096
#define TM 128
#define TN 128
#define NTHR 512

__device__ __align__(16) __nv_bfloat16 g_xbf[MAX_T * C_DIM];  // zero-init: rows>=T are 0
__device__ float g_rowsum[MAX_T];
__device__ float g_pairpart[128];
__device__ int   g_cnt;                // zero-init; self-resetting

// smem: 3 stages x (A 32KB + B 32KB) = 192KB
#define STAGE_BYTES 65536
#define SMEM_DYN (3 * STAGE_BYTES)

// ---------------- helpers ----------------
__device__ __forceinline__ uint32_t smem_u32(const void* p) {
    uint32_t a;
    asm("{ .reg .u64 t; cvta.to.shared.u64 t, %1; cvt.u32.u64 %0, t; }" : "=r"(a) : "l"(p));
    return a;
}

__device__ __forceinline__ void cp_async16(uint32_t dst, const void* src) {
    asm volatile("cp.async.cg.shared.global [%0], [%1], 16;"
                 :: "r"(dst), "l"(__cvta_generic_to_global(src)));
}
#define CP_COMMIT()  asm volatile("cp.async.commit_group;" ::: "memory")
#define CP_WAIT(n)   asm volatile("cp.async.wait_group %0;" :: "n"(n) : "memory")

__device__ __forceinline__ void ldmatrix_x4(uint32_t* r, uint32_t addr) {
    asm volatile("ldmatrix.sync.aligned.m8n8.x4.shared.b16 {%0,%1,%2,%3}, [%4];"
                 : "=r"(r[0]), "=r"(r[1]), "=r"(r[2]), "=r"(r[3]) : "r"(addr));
}

__device__ __forceinline__ void mma_bf16(float* c, const uint32_t* a, const uint32_t* b) {
    asm volatile(
        "mma.sync.aligned.m16n8k16.row.col.f32.bf16.bf16.f32 "
        "{%0,%1,%2,%3}, {%4,%5,%6,%7}, {%8,%9}, {%0,%1,%2,%3};"
        : "+f"(c[0]), "+f"(c[1]), "+f"(c[2]), "+f"(c[3])
        : "r"(a[0]), "r"(a[1]), "r"(a[2]), "r"(a[3]), "r"(b[0]), "r"(b[1]));
}

// ---------------- fp32x2 packed math ----------------
__device__ __forceinline__ unsigned long long pk2(float lo, float hi) {
    unsigned long long r;
    asm("mov.b64 %0, {%1, %2};" : "=l"(r) : "f"(lo), "f"(hi));
    return r;
}
__device__ __forceinline__ float2 up2(unsigned long long v) {
    float2 r;
    asm("mov.b64 {%0, %1}, %2;" : "=f"(r.x), "=f"(r.y) : "l"(v));
    return r;
}
__device__ __forceinline__ unsigned long long fma2(unsigned long long a,
                                                   unsigned long long b,
                                                   unsigned long long c) {
    unsigned long long d;
    asm("fma.rn.f32x2 %0, %1, %2, %3;" : "=l"(d) : "l"(a), "l"(b), "l"(c));
    return d;
}
__device__ __forceinline__ unsigned long long add2(unsigned long long a,
                                                   unsigned long long b) {
    unsigned long long d;
    asm("add.rn.f32x2 %0, %1, %2;" : "=l"(d) : "l"(a), "l"(b));
    return d;
}
// exp(c) for |c| <= ~1.05, degree-6 Taylor; exp_pk(0) == 1.0 exactly.
__device__ __forceinline__ unsigned long long exp_pk(unsigned long long c) {
    unsigned long long p = pk2(1.3888889e-3f, 1.3888889e-3f);   // 1/6!
    p = fma2(p, c, pk2(8.3333333e-3f, 8.3333333e-3f));          // 1/5!
    p = fma2(p, c, pk2(4.1666667e-2f, 4.1666667e-2f));          // 1/4!
    p = fma2(p, c, pk2(1.6666667e-1f, 1.6666667e-1f));          // 1/3!
    p = fma2(p, c, pk2(0.5f, 0.5f));
    p = fma2(p, c, pk2(1.0f, 1.0f));
    p = fma2(p, c, pk2(1.0f, 1.0f));
    return p;
}

// tile smem layout: row-major 128 rows x 256B, 16B chunks XOR-swizzled by (row&7)
__device__ __forceinline__ void copy_tile_async(uint32_t dstb, int grow0, int tid) {
    #pragma unroll
    for (int l = 0; l < 4; l++) {
        int idx = tid + l * NTHR;              // 0..2047
        int row = idx >> 4;
        int ch  = idx & 15;
        cp_async16(dstb + row * 256 + ((ch ^ (row & 7)) << 4),
                   &g_xbf[(grow0 + row) * C_DIM + ch * 8]);
    }
}

// flat upper-triangle index -> (it, jt), jt >= it
__device__ __forceinline__ void tri_decode(int f, int ntM, int& it, int& jt) {
    int i = 0;
    while (f >= ntM - i) { f -= ntM - i; i++; }
    it = i; jt = i + f;
}

// ---------------- kernels ----------------
__global__ __launch_bounds__(128) void normalize_kernel(const float* __restrict__ x, int T) {
    int gid = blockIdx.x * 128 + threadIdx.x;
    if (gid < MAX_T) g_rowsum[gid] = 0.f;      // per-replay reset
    int row  = blockIdx.x * 4 + (threadIdx.x >> 5);
    int lane = threadIdx.x & 31;
    if (row < T) {
        float4 v = *(const float4*)&x[row * C_DIM + lane * 4];
        float s = v.x * v.x + v.y * v.y + v.z * v.z + v.w * v.w;
        #pragma unroll
        for (int o = 16; o > 0; o >>= 1) s += __shfl_xor_sync(0xffffffffu, s, o);
        float inv = 1.0f / fmaxf(sqrtf(s), 1e-8f);
        __nv_bfloat162 o0 = __floats2bfloat162_rn(v.x * inv, v.y * inv);
        __nv_bfloat162 o1 = __floats2bfloat162_rn(v.z * inv, v.w * inv);
        uint2 pk;
        pk.x = *(uint32_t*)&o0;
        pk.y = *(uint32_t*)&o1;
        *(uint2*)&g_xbf[row * C_DIM + lane * 4] = pk;
    }
}

__global__ __launch_bounds__(NTHR) void rowsum_tri(int T, int ntM, int G) {
    extern __shared__ char smem[];
    const uint32_t sb = smem_u32(smem);
    const int tid  = threadIdx.x;
    const int wid  = tid >> 5;                 // 0..15
    const int lane = tid & 31;
    const int bid  = blockIdx.x;

    const int NT = ntM * (ntM + 1) / 2;
    const int nmine = (bid < NT) ? ((NT - bid - 1) / G + 1) : 0;
    if (nmine == 0) return;

    // prologue: prefetch tiles 0,1
    #pragma unroll
    for (int s = 0; s < 2; s++) {
        if (s < nmine) {
            int it, jt; tri_decode(bid + s * G, ntM, it, jt);
            uint32_t base = sb + s * STAGE_BYTES;
            copy_tile_async(base, it * TM, tid);
            copy_tile_async(base + 32768, jt * TN, tid);
            CP_COMMIT();
        }
    }

    const int mq = wid >> 2;                   // M quarter: 32 rows
    const int nq = wid & 3;                    // N quarter: 32 cols
    const int mrow = mq * 32;
    const int jw   = nq * 32;
    const int s7   = lane & 7;

    const int ro_a = (lane & 7) + ((lane >> 3) & 1) * 8;
    const int cg_a = (lane >> 4);
    const int ro_b = (lane & 7) + ((lane >> 4) & 1) * 8;
    const int cg_b = (lane >> 3) & 1;

    for (int s = 0; s < nmine; s++) {
        int it, jt; tri_decode(bid + s * G, ntM, it, jt);
        const int i0 = it * TM, j0 = jt * TN;

        if (s + 1 < nmine) { CP_WAIT(1); } else { CP_WAIT(0); }
        __syncthreads();

        if (s + 2 < nmine) {
            int it2, jt2; tri_decode(bid + (s + 2) * G, ntM, it2, jt2);
            uint32_t base2 = sb + ((s + 2) % 3) * STAGE_BYTES;
            copy_tile_async(base2, it2 * TM, tid);
            copy_tile_async(base2 + 32768, jt2 * TN, tid);
            CP_COMMIT();
        }

        const uint32_t ab = sb + (s % 3) * STAGE_BYTES;
        const uint32_t bb = ab + 32768;
        uint32_t a_addr[2], b_addr[2];
        #pragma unroll
        for (int mi = 0; mi < 2; mi++)
            a_addr[mi] = ab + (mrow + mi * 16 + ro_a) * 256;
        #pragma unroll
        for (int p = 0; p < 2; p++)
            b_addr[p] = bb + (jw + p * 16 + ro_b) * 256;

        float c[2][4][4];
        #pragma unroll
        for (int mi = 0; mi < 2; mi++)
            #pragma unroll
            for (int ni = 0; ni < 4; ni++)
                #pragma unroll
                for (int q = 0; q < 4; q++) c[mi][ni][q] = 0.f;

        #pragma unroll
        for (int ks = 0; ks < 8; ks++) {
            const uint32_t chA = (uint32_t)(((ks * 2 + cg_a) ^ s7) << 4);
            const uint32_t chB = (uint32_t)(((ks * 2 + cg_b) ^ s7) << 4);
            uint32_t a[2][4], b[2][4];
            #pragma unroll
            for (int mi = 0; mi < 2; mi++) ldmatrix_x4(a[mi], a_addr[mi] + chA);
            #pragma unroll
            for (int p = 0; p < 2; p++)    ldmatrix_x4(b[p], b_addr[p] + chB);
            #pragma unroll
            for (int mi = 0; mi < 2; mi++)
                #pragma unroll
                for (int ni = 0; ni < 4; ni++)
                    mma_bf16(c[mi][ni], a[mi], &b[ni >> 1][(ni & 1) * 2]);
        }

        // ---- epilogue: exp once; feed row sums and (off-diag) col sums ----
        unsigned long long racc[4] = {0ull, 0ull, 0ull, 0ull};
        unsigned long long cacc[4] = {0ull, 0ull, 0ull, 0ull};
        #pragma unroll
        for (int mi = 0; mi < 2; mi++)
            #pragma unroll
            for (int ni = 0; ni < 4; ni++) {
                unsigned long long e01 = exp_pk(pk2(c[mi][ni][0], c[mi][ni][1]));
                unsigned long long e23 = exp_pk(pk2(c[mi][ni][2], c[mi][ni][3]));
                racc[mi * 2]     = add2(racc[mi * 2], e01);
                racc[mi * 2 + 1] = add2(racc[mi * 2 + 1], e23);
                cacc[ni]         = add2(cacc[ni], add2(e01, e23));
            }

        // row sums: subtract padded (col >= T) contributions of THIS lane strip
        int padc = 0;
        if (j0 + TN > T) {
            #pragma unroll
            for (int ni = 0; ni < 4; ni++) {
                int col = j0 + jw + ni * 8 + 2 * (lane & 3);
                padc += (col >= T) + (col + 1 >= T);
            }
        }
        float rrow[4];
        #pragma unroll
        for (int q = 0; q < 4; q++) {
            float2 u = up2(racc[q]);
            rrow[q] = (u.x + u.y) - (float)padc;
            rrow[q] += __shfl_xor_sync(0xffffffffu, rrow[q], 1);
            rrow[q] += __shfl_xor_sync(0xffffffffu, rrow[q], 2);
        }
        if ((lane & 3) == 0) {
            int rbase = i0 + mrow + (lane >> 2);
            #pragma unroll
            for (int mi = 0; mi < 2; mi++)
                #pragma unroll
                for (int h = 0; h < 2; h++) {
                    int row = rbase + mi * 16 + h * 8;
                    if (row < T) atomicAdd(&g_rowsum[row], rrow[mi * 2 + h]);
                }
        }

        // col sums (symmetry) for off-diagonal tiles
        if (it != jt) {
            float padr = (float)min(32, max(0, i0 + mrow + 32 - T));
            #pragma unroll
            for (int ni = 0; ni < 4; ni++) {
                float2 u = up2(cacc[ni]);
                #pragma unroll
                for (int o = 4; o <= 16; o <<= 1) {
                    u.x += __shfl_xor_sync(0xffffffffu, u.x, o);
                    u.y += __shfl_xor_sync(0xffffffffu, u.y, o);
                }
                if (lane < 4) {
                    int col = j0 + jw + ni * 8 + 2 * lane;
                    if (col < T)     atomicAdd(&g_rowsum[col],     u.x - padr);
                    if (col + 1 < T) atomicAdd(&g_rowsum[col + 1], u.y - padr);
                }
            }
        }
    }
}

// warp-per-block: in-block cosines (fp32 dots over the same bf16 data) + loss
// terms; counter-fused final reduction writes out.
__global__ __launch_bounds__(256) void pairs_finalize(
    float rscale, int Bnum, int ncta, const int* __restrict__ kuai2,
    float* __restrict__ out)
{
    const int lane = threadIdx.x & 31;
    const int wid  = threadIdx.x >> 5;
    const int b    = blockIdx.x * 8 + wid;

    float warp_term = 0.f;
    if (b < Bnum) {
        float4 u[BLK];
        #pragma unroll
        for (int m = 0; m < BLK; m++) {
            const __nv_bfloat162* p =
                (const __nv_bfloat162*)&g_xbf[(b * BLK + m) * C_DIM + lane * 4];
            float2 lo = __bfloat1622float2(p[0]);
            float2 hi = __bfloat1622float2(p[1]);
            u[m] = make_float4(lo.x, lo.y, hi.x, hi.y);
        }
        float cm[BLK][BLK];
        #pragma unroll
        for (int i = 0; i < BLK; i++)
            #pragma unroll
            for (int j = i; j < BLK; j++) {
                float s = u[i].x * u[j].x + u[i].y * u[j].y
                        + u[i].z * u[j].z + u[i].w * u[j].w;
                #pragma unroll
                for (int o = 16; o > 0; o >>= 1) s += __shfl_xor_sync(0xffffffffu, s, o);
                cm[i][j] = s; cm[j][i] = s;
            }
        float term = 0.f;
        if (lane < BLK) {
            int i = lane;
            float es[BLK], bsum = 0.f;
            #pragma unroll
            for (int m = 0; m < BLK; m++) { es[m] = expf(cm[i][m]); bsum += es[m]; }
            float rs = g_rowsum[b * BLK + i];
            float negA = rscale * (rs - bsum);
            #pragma unroll
            for (int m = 0; m < BLK; m++)
                if (m != i) term += logf(es[m] + negA) - cm[i][m];
        }
        #pragma unroll
        for (int o = 16; o > 0; o >>= 1) term += __shfl_xor_sync(0xffffffffu, term, o);
        warp_term = term;
    }

    __shared__ float ws[8];
    __shared__ int s_fin;
    if (lane == 0) ws[wid] = warp_term;
    __syncthreads();
    if (threadIdx.x == 0) {
        float s = 0.f;
        #pragma unroll
        for (int k = 0; k < 8; k++) s += ws[k];
        g_pairpart[blockIdx.x] = s;
        __threadfence();
        int o = atomicAdd(&g_cnt, 1);
        s_fin = (o == ncta - 1);
        if (s_fin) g_cnt = 0;                  // reset for next replay
    }
    __syncthreads();
    if (s_fin && threadIdx.x < 32) {
        __threadfence();
        double s = 0.0;
        for (int i = threadIdx.x; i < ncta; i += 32) s += (double)g_pairpart[i];
        #pragma unroll
        for (int o = 16; o > 0; o >>= 1) s += __shfl_xor_sync(0xffffffffu, s, o);
        if (threadIdx.x == 0) {
            int k2 = *kuai2;
            out[0] = (float)(s / ((double)Bnum * (double)k2 * (double)(k2 - 1)));
        }
    }
}

// ---------------- launch ----------------
extern "C" void kernel_launch(void* const* d_in, const int* in_sizes, int n_in,
                              void* d_out, int out_size) {
    const float* x     = (const float*)d_in[0];
    const int*   kuai2 = (const int*)d_in[1];

    int T = in_sizes[0] / C_DIM;
    int B = T / BLK;
    float r = (float)(2 * B - 2) / (float)(T - BLK);
    int ntM = (T + TM - 1) / TM;
    int NT  = ntM * (ntM + 1) / 2;
    int G   = (NT < 132) ? NT : 132;
    int ncta_pairs = (B + 7) / 8;

    cudaFuncSetAttribute(rowsum_tri, cudaFuncAttributeMaxDynamicSharedMemorySize, SMEM_DYN);

    normalize_kernel<<<(T + 3) / 4, 128>>>(x, T);
    rowsum_tri<<<G, NTHR, SMEM_DYN>>>(T, ntM, G);
    pairs_finalize<<<ncta_pairs, 256>>>(r, B, ncta_pairs, kuai2, (float*)d_out);
}

// round 9
// speedup vs baseline: 1.9011x; 1.0887x over previous
#include <cuda_runtime.h>
#include <cuda_bf16.h>
#include <cstdint>

// ---------------------------------------------------------------------------
// loss2, 3 launches:
//   1) normalize -> bf16 (warp per row, 512-thr blocks) + zero g_rowsum
//   2) rowsum GEMM over UPPER-TRIANGLE tile-pairs (symmetry): bf16 mma.sync,
//      512 threads, 32x64 warp tiles over 128x256 jobs (A 32KB + B 64KB per
//      stage, double buffered, both jobs prefetched in prologue), packed-f32x2
//      degree-6 exp epilogue feeding row sums + (off-diag) col sums via
//      fp32 atomicAdd into g_rowsum.
//   3) pairs+finalize (counter-fused) -> out
// ---------------------------------------------------------------------------

#define C_DIM 128
#define BLK 5
#define MAX_T 4096
#define TM 128
#define NTHR 512

__device__ __align__(16) __nv_bfloat16 g_xbf[MAX_T * C_DIM];  // zero-init: rows>=T are 0
__device__ float g_rowsum[MAX_T];
__device__ float g_pairpart[128];
__device__ int   g_cnt;                // zero-init; self-resetting

// smem: 2 stages x (A 32KB + B 64KB) = 192KB
#define STAGE_BYTES 98304
#define SMEM_DYN (2 * STAGE_BYTES)

// ---------------- helpers ----------------
__device__ __forceinline__ uint32_t smem_u32(const void* p) {
    uint32_t a;
    asm("{ .reg .u64 t; cvta.to.shared.u64 t, %1; cvt.u32.u64 %0, t; }" : "=r"(a) : "l"(p));
    return a;
}

__device__ __forceinline__ void cp_async16(uint32_t dst, const void* src) {
    asm volatile("cp.async.cg.shared.global [%0], [%1], 16;"
                 :: "r"(dst), "l"(__cvta_generic_to_global(src)));
}
#define CP_COMMIT()  asm volatile("cp.async.commit_group;" ::: "memory")
#define CP_WAIT(n)   asm volatile("cp.async.wait_group %0;" :: "n"(n) : "memory")

__device__ __forceinline__ void ldmatrix_x4(uint32_t* r, uint32_t addr) {
    asm volatile("ldmatrix.sync.aligned.m8n8.x4.shared.b16 {%0,%1,%2,%3}, [%4];"
                 : "=r"(r[0]), "=r"(r[1]), "=r"(r[2]), "=r"(r[3]) : "r"(addr));
}

__device__ __forceinline__ void mma_bf16(float* c, const uint32_t* a, const uint32_t* b) {
    asm volatile(
        "mma.sync.aligned.m16n8k16.row.col.f32.bf16.bf16.f32 "
        "{%0,%1,%2,%3}, {%4,%5,%6,%7}, {%8,%9}, {%0,%1,%2,%3};"
        : "+f"(c[0]), "+f"(c[1]), "+f"(c[2]), "+f"(c[3])
        : "r"(a[0]), "r"(a[1]), "r"(a[2]), "r"(a[3]), "r"(b[0]), "r"(b[1]));
}

// ---------------- fp32x2 packed math ----------------
__device__ __forceinline__ unsigned long long pk2(float lo, float hi) {
    unsigned long long r;
    asm("mov.b64 %0, {%1, %2};" : "=l"(r) : "f"(lo), "f"(hi));
    return r;
}
__device__ __forceinline__ float2 up2(unsigned long long v) {
    float2 r;
    asm("mov.b64 {%0, %1}, %2;" : "=f"(r.x), "=f"(r.y) : "l"(v));
    return r;
}
__device__ __forceinline__ unsigned long long fma2(unsigned long long a,
                                                   unsigned long long b,
                                                   unsigned long long c) {
    unsigned long long d;
    asm("fma.rn.f32x2 %0, %1, %2, %3;" : "=l"(d) : "l"(a), "l"(b), "l"(c));
    return d;
}
__device__ __forceinline__ unsigned long long add2(unsigned long long a,
                                                   unsigned long long b) {
    unsigned long long d;
    asm("add.rn.f32x2 %0, %1, %2;" : "=l"(d) : "l"(a), "l"(b));
    return d;
}
// exp(c) for |c| <= ~1.05, degree-6 Taylor; exp_pk(0) == 1.0 exactly.
__device__ __forceinline__ unsigned long long exp_pk(unsigned long long c) {
    unsigned long long p = pk2(1.3888889e-3f, 1.3888889e-3f);   // 1/6!
    p = fma2(p, c, pk2(8.3333333e-3f, 8.3333333e-3f));          // 1/5!
    p = fma2(p, c, pk2(4.1666667e-2f, 4.1666667e-2f));          // 1/4!
    p = fma2(p, c, pk2(1.6666667e-1f, 1.6666667e-1f));          // 1/3!
    p = fma2(p, c, pk2(0.5f, 0.5f));
    p = fma2(p, c, pk2(1.0f, 1.0f));
    p = fma2(p, c, pk2(1.0f, 1.0f));
    return p;
}

// tile smem layout: row-major 128 rows x 256B, 16B chunks XOR-swizzled by (row&7)
__device__ __forceinline__ void copy_tile_async(uint32_t dstb, int grow0, int tid) {
    #pragma unroll
    for (int l = 0; l < 4; l++) {
        int idx = tid + l * NTHR;              // 0..2047
        int row = idx >> 4;
        int ch  = idx & 15;
        cp_async16(dstb + row * 256 + ((ch ^ (row & 7)) << 4),
                   &g_xbf[(grow0 + row) * C_DIM + ch * 8]);
    }
}

// flat job index -> (it, jt0, njt): panel it, pair q covers jt = it+2q, it+2q+1
__device__ __forceinline__ void job_decode(int f, int ntM, int& it, int& jt0, int& njt) {
    int i = 0;
    for (;;) {
        int pairs = (ntM - i + 1) >> 1;
        if (f < pairs) { it = i; jt0 = i + f * 2; njt = min(2, ntM - jt0); return; }
        f -= pairs; ++i;
    }
}

// ---------------- kernels ----------------
__global__ __launch_bounds__(512) void normalize_kernel(const float* __restrict__ x, int T) {
    int gid = blockIdx.x * 512 + threadIdx.x;
    if (gid < MAX_T) g_rowsum[gid] = 0.f;      // per-replay reset
    int row  = blockIdx.x * 16 + (threadIdx.x >> 5);
    int lane = threadIdx.x & 31;
    if (row < T) {
        float4 v = *(const float4*)&x[row * C_DIM + lane * 4];
        float s = v.x * v.x + v.y * v.y + v.z * v.z + v.w * v.w;
        #pragma unroll
        for (int o = 16; o > 0; o >>= 1) s += __shfl_xor_sync(0xffffffffu, s, o);
        float inv = 1.0f / fmaxf(sqrtf(s), 1e-8f);
        __nv_bfloat162 o0 = __floats2bfloat162_rn(v.x * inv, v.y * inv);
        __nv_bfloat162 o1 = __floats2bfloat162_rn(v.z * inv, v.w * inv);
        uint2 pk;
        pk.x = *(uint32_t*)&o0;
        pk.y = *(uint32_t*)&o1;
        *(uint2*)&g_xbf[row * C_DIM + lane * 4] = pk;
    }
}

__global__ __launch_bounds__(NTHR) void rowsum_tri(int T, int ntM, int G, int NJ) {
    extern __shared__ char smem[];
    const uint32_t sb = smem_u32(smem);
    const int tid  = threadIdx.x;
    const int wid  = tid >> 5;                 // 0..15
    const int lane = tid & 31;
    const int bid  = blockIdx.x;

    const int njobs = (bid < NJ ? 1 : 0) + (bid + G < NJ ? 1 : 0);
    if (njobs == 0) return;

    // prologue: prefetch both jobs (each job = A tile + 1 or 2 B tiles)
    for (int s = 0; s < njobs; s++) {
        int it, jt0, njt; job_decode(bid + s * G, ntM, it, jt0, njt);
        uint32_t base = sb + s * STAGE_BYTES;
        copy_tile_async(base, it * TM, tid);
        copy_tile_async(base + 32768, jt0 * TM, tid);
        if (njt == 2) copy_tile_async(base + 65536, (jt0 + 1) * TM, tid);
        CP_COMMIT();
    }

    const int mq = wid >> 2;                   // M quarter: 32 rows
    const int nc = wid & 3;                    // N chunk:   64 cols of 256
    const int mrow = mq * 32;
    const int s7   = lane & 7;

    const int ro_a = (lane & 7) + ((lane >> 3) & 1) * 8;
    const int cg_a = (lane >> 4);
    const int ro_b = (lane & 7) + ((lane >> 4) & 1) * 8;
    const int cg_b = (lane >> 3) & 1;

    for (int s = 0; s < njobs; s++) {
        int it, jt0, njt; job_decode(bid + s * G, ntM, it, jt0, njt);
        const int i0 = it * TM;

        if (s + 1 < njobs) { CP_WAIT(1); } else { CP_WAIT(0); }
        __syncthreads();

        const bool active = (nc >> 1) < njt;
        if (active) {
            const uint32_t ab = sb + s * STAGE_BYTES;
            const uint32_t bt = ab + 32768 + (nc >> 1) * 32768;  // this warp's B tile
            const int jloc = (nc & 1) * 64;                       // col base in B tile
            const int jt   = jt0 + (nc >> 1);                     // global 128-col tile
            const int gj0  = jt * TM + jloc;                      // global col base

            uint32_t a_addr[2], b_addr[4];
            #pragma unroll
            for (int mi = 0; mi < 2; mi++)
                a_addr[mi] = ab + (mrow + mi * 16 + ro_a) * 256;
            #pragma unroll
            for (int p = 0; p < 4; p++)
                b_addr[p] = bt + (jloc + p * 16 + ro_b) * 256;

            float c[2][8][4];
            #pragma unroll
            for (int mi = 0; mi < 2; mi++)
                #pragma unroll
                for (int ni = 0; ni < 8; ni++)
                    #pragma unroll
                    for (int q = 0; q < 4; q++) c[mi][ni][q] = 0.f;

            #pragma unroll
            for (int ks = 0; ks < 8; ks++) {
                const uint32_t chA = (uint32_t)(((ks * 2 + cg_a) ^ s7) << 4);
                const uint32_t chB = (uint32_t)(((ks * 2 + cg_b) ^ s7) << 4);
                uint32_t a[2][4], b[4][4];
                #pragma unroll
                for (int mi = 0; mi < 2; mi++) ldmatrix_x4(a[mi], a_addr[mi] + chA);
                #pragma unroll
                for (int p = 0; p < 4; p++)    ldmatrix_x4(b[p], b_addr[p] + chB);
                #pragma unroll
                for (int mi = 0; mi < 2; mi++)
                    #pragma unroll
                    for (int ni = 0; ni < 8; ni++)
                        mma_bf16(c[mi][ni], a[mi], &b[ni >> 1][(ni & 1) * 2]);
            }

            // ---- epilogue: exp once; row sums + (off-diag) col sums ----
            unsigned long long racc[4] = {0ull, 0ull, 0ull, 0ull};
            unsigned long long cacc[8] = {0ull,0ull,0ull,0ull,0ull,0ull,0ull,0ull};
            #pragma unroll
            for (int mi = 0; mi < 2; mi++)
                #pragma unroll
                for (int ni = 0; ni < 8; ni++) {
                    unsigned long long e01 = exp_pk(pk2(c[mi][ni][0], c[mi][ni][1]));
                    unsigned long long e23 = exp_pk(pk2(c[mi][ni][2], c[mi][ni][3]));
                    racc[mi * 2]     = add2(racc[mi * 2], e01);
                    racc[mi * 2 + 1] = add2(racc[mi * 2 + 1], e23);
                    cacc[ni]         = add2(cacc[ni], add2(e01, e23));
                }

            // row sums: subtract padded (col >= T) contributions of this lane
            int padc = 0;
            if (gj0 + 64 > T) {
                #pragma unroll
                for (int ni = 0; ni < 8; ni++) {
                    int col = gj0 + ni * 8 + 2 * (lane & 3);
                    padc += (col >= T) + (col + 1 >= T);
                }
            }
            float rrow[4];
            #pragma unroll
            for (int q = 0; q < 4; q++) {
                float2 u = up2(racc[q]);
                rrow[q] = (u.x + u.y) - (float)padc;
                rrow[q] += __shfl_xor_sync(0xffffffffu, rrow[q], 1);
                rrow[q] += __shfl_xor_sync(0xffffffffu, rrow[q], 2);
            }
            if ((lane & 3) == 0) {
                int rbase = i0 + mrow + (lane >> 2);
                #pragma unroll
                for (int mi = 0; mi < 2; mi++)
                    #pragma unroll
                    for (int h = 0; h < 2; h++) {
                        int row = rbase + mi * 16 + h * 8;
                        if (row < T) atomicAdd(&g_rowsum[row], rrow[mi * 2 + h]);
                    }
            }

            // col sums (symmetry) — skip the diagonal 128-tile
            if (jt != it) {
                float padr = (float)min(32, max(0, i0 + mrow + 32 - T));
                #pragma unroll
                for (int ni = 0; ni < 8; ni++) {
                    float2 u = up2(cacc[ni]);
                    #pragma unroll
                    for (int o = 4; o <= 16; o <<= 1) {
                        u.x += __shfl_xor_sync(0xffffffffu, u.x, o);
                        u.y += __shfl_xor_sync(0xffffffffu, u.y, o);
                    }
                    if (lane < 4) {
                        int col = gj0 + ni * 8 + 2 * lane;
                        if (col < T)     atomicAdd(&g_rowsum[col],     u.x - padr);
                        if (col + 1 < T) atomicAdd(&g_rowsum[col + 1], u.y - padr);
                    }
                }
            }
        }
    }
}

// warp-per-block: in-block cosines (fp32 dots over the same bf16 data) + loss
// terms; counter-fused final reduction writes out.
__global__ __launch_bounds__(256) void pairs_finalize(
    float rscale, int Bnum, int ncta, const int* __restrict__ kuai2,
    float* __restrict__ out)
{
    const int lane = threadIdx.x & 31;
    const int wid  = threadIdx.x >> 5;
    const int b    = blockIdx.x * 8 + wid;

    float warp_term = 0.f;
    if (b < Bnum) {
        float4 u[BLK];
        #pragma unroll
        for (int m = 0; m < BLK; m++) {
            const __nv_bfloat162* p =
                (const __nv_bfloat162*)&g_xbf[(b * BLK + m) * C_DIM + lane * 4];
            float2 lo = __bfloat1622float2(p[0]);
            float2 hi = __bfloat1622float2(p[1]);
            u[m] = make_float4(lo.x, lo.y, hi.x, hi.y);
        }
        float cm[BLK][BLK];
        #pragma unroll
        for (int i = 0; i < BLK; i++)
            #pragma unroll
            for (int j = i; j < BLK; j++) {
                float s = u[i].x * u[j].x + u[i].y * u[j].y
                        + u[i].z * u[j].z + u[i].w * u[j].w;
                #pragma unroll
                for (int o = 16; o > 0; o >>= 1) s += __shfl_xor_sync(0xffffffffu, s, o);
                cm[i][j] = s; cm[j][i] = s;
            }
        float term = 0.f;
        if (lane < BLK) {
            int i = lane;
            float es[BLK], bsum = 0.f;
            #pragma unroll
            for (int m = 0; m < BLK; m++) { es[m] = expf(cm[i][m]); bsum += es[m]; }
            float rs = g_rowsum[b * BLK + i];
            float negA = rscale * (rs - bsum);
            #pragma unroll
            for (int m = 0; m < BLK; m++)
                if (m != i) term += logf(es[m] + negA) - cm[i][m];
        }
        #pragma unroll
        for (int o = 16; o > 0; o >>= 1) term += __shfl_xor_sync(0xffffffffu, term, o);
        warp_term = term;
    }

    __shared__ float ws[8];
    __shared__ int s_fin;
    if (lane == 0) ws[wid] = warp_term;
    __syncthreads();
    if (threadIdx.x == 0) {
        float s = 0.f;
        #pragma unroll
        for (int k = 0; k < 8; k++) s += ws[k];
        g_pairpart[blockIdx.x] = s;
        __threadfence();
        int o = atomicAdd(&g_cnt, 1);
        s_fin = (o == ncta - 1);
        if (s_fin) g_cnt = 0;                  // reset for next replay
    }
    __syncthreads();
    if (s_fin && threadIdx.x < 32) {
        __threadfence();
        double s = 0.0;
        for (int i = threadIdx.x; i < ncta; i += 32) s += (double)g_pairpart[i];
        #pragma unroll
        for (int o = 16; o > 0; o >>= 1) s += __shfl_xor_sync(0xffffffffu, s, o);
        if (threadIdx.x == 0) {
            int k2 = *kuai2;
            out[0] = (float)(s / ((double)Bnum * (double)k2 * (double)(k2 - 1)));
        }
    }
}

// ---------------- launch ----------------
extern "C" void kernel_launch(void* const* d_in, const int* in_sizes, int n_in,
                              void* d_out, int out_size) {
    const float* x     = (const float*)d_in[0];
    const int*   kuai2 = (const int*)d_in[1];

    int T = in_sizes[0] / C_DIM;
    int B = T / BLK;
    float r = (float)(2 * B - 2) / (float)(T - BLK);
    int ntM = (T + TM - 1) / TM;

    int NJ = 0;
    for (int i = 0; i < ntM; i++) NJ += (ntM - i + 1) >> 1;   // job (pair) count
    int G = (NJ < 148) ? NJ : 148;                            // <=2 jobs per CTA
    int ncta_pairs = (B + 7) / 8;

    cudaFuncSetAttribute(rowsum_tri, cudaFuncAttributeMaxDynamicSharedMemorySize, SMEM_DYN);

    normalize_kernel<<<(T + 15) / 16, 512>>>(x, T);
    rowsum_tri<<<G, NTHR, SMEM_DYN>>>(T, ntM, G, NJ);
    pairs_finalize<<<ncta_pairs, 256>>>(r, B, ncta_pairs, kuai2, (float*)d_out);
}

// round 10
// speedup vs baseline: 1.9531x; 1.0273x over previous
#include <cuda_runtime.h>
#include <cuda_bf16.h>
#include <cstdint>

// ---------------------------------------------------------------------------
// loss2, 3 launches:
//   1) normalize -> bf16 (8 threads/row, MLP=4) + zero g_rowsum
//   2) rowsum GEMM over UPPER-TRIANGLE tile chunks (symmetry): bf16 mma.sync,
//      256 threads / 8 warps, 2 CTAs/SM (96KB smem) so one CTA's epilogue
//      overlaps the other's MMA mainloop. Chunk = A panel + up to 2 B tiles
//      (sequential, prefetched). Packed-f32x2 degree-6 exp epilogue feeds row
//      sums + (off-diag) col sums via fp32 atomicAdd into g_rowsum.
//   3) pairs+finalize (counter-fused) -> out
// ---------------------------------------------------------------------------

#define C_DIM 128
#define BLK 5
#define MAX_T 4096
#define TM 128
#define NTHR 256

__device__ __align__(16) __nv_bfloat16 g_xbf[MAX_T * C_DIM];  // zero-init: rows>=T are 0
__device__ float g_rowsum[MAX_T];
__device__ float g_pairpart[128];
__device__ int   g_cnt;                // zero-init; self-resetting

// smem: A 32KB @0, B tiles @32768 and @65536
#define OFF_A  0
#define OFF_B0 32768
#define OFF_B1 65536
#define SMEM_DYN 98304

// ---------------- helpers ----------------
__device__ __forceinline__ uint32_t smem_u32(const void* p) {
    uint32_t a;
    asm("{ .reg .u64 t; cvta.to.shared.u64 t, %1; cvt.u32.u64 %0, t; }" : "=r"(a) : "l"(p));
    return a;
}

__device__ __forceinline__ void cp_async16(uint32_t dst, const void* src) {
    asm volatile("cp.async.cg.shared.global [%0], [%1], 16;"
                 :: "r"(dst), "l"(__cvta_generic_to_global(src)));
}
#define CP_COMMIT()  asm volatile("cp.async.commit_group;" ::: "memory")
#define CP_WAIT(n)   asm volatile("cp.async.wait_group %0;" :: "n"(n) : "memory")

__device__ __forceinline__ void ldmatrix_x4(uint32_t* r, uint32_t addr) {
    asm volatile("ldmatrix.sync.aligned.m8n8.x4.shared.b16 {%0,%1,%2,%3}, [%4];"
                 : "=r"(r[0]), "=r"(r[1]), "=r"(r[2]), "=r"(r[3]) : "r"(addr));
}

__device__ __forceinline__ void mma_bf16(float* c, const uint32_t* a, const uint32_t* b) {
    asm volatile(
        "mma.sync.aligned.m16n8k16.row.col.f32.bf16.bf16.f32 "
        "{%0,%1,%2,%3}, {%4,%5,%6,%7}, {%8,%9}, {%0,%1,%2,%3};"
        : "+f"(c[0]), "+f"(c[1]), "+f"(c[2]), "+f"(c[3])
        : "r"(a[0]), "r"(a[1]), "r"(a[2]), "r"(a[3]), "r"(b[0]), "r"(b[1]));
}

// ---------------- fp32x2 packed math ----------------
__device__ __forceinline__ unsigned long long pk2(float lo, float hi) {
    unsigned long long r;
    asm("mov.b64 %0, {%1, %2};" : "=l"(r) : "f"(lo), "f"(hi));
    return r;
}
__device__ __forceinline__ float2 up2(unsigned long long v) {
    float2 r;
    asm("mov.b64 {%0, %1}, %2;" : "=f"(r.x), "=f"(r.y) : "l"(v));
    return r;
}
__device__ __forceinline__ unsigned long long fma2(unsigned long long a,
                                                   unsigned long long b,
                                                   unsigned long long c) {
    unsigned long long d;
    asm("fma.rn.f32x2 %0, %1, %2, %3;" : "=l"(d) : "l"(a), "l"(b), "l"(c));
    return d;
}
__device__ __forceinline__ unsigned long long add2(unsigned long long a,
                                                   unsigned long long b) {
    unsigned long long d;
    asm("add.rn.f32x2 %0, %1, %2;" : "=l"(d) : "l"(a), "l"(b));
    return d;
}
// exp(c) for |c| <= ~1.05, degree-6 Taylor; exp_pk(0) == 1.0 exactly.
__device__ __forceinline__ unsigned long long exp_pk(unsigned long long c) {
    unsigned long long p = pk2(1.3888889e-3f, 1.3888889e-3f);   // 1/6!
    p = fma2(p, c, pk2(8.3333333e-3f, 8.3333333e-3f));          // 1/5!
    p = fma2(p, c, pk2(4.1666667e-2f, 4.1666667e-2f));          // 1/4!
    p = fma2(p, c, pk2(1.6666667e-1f, 1.6666667e-1f));          // 1/3!
    p = fma2(p, c, pk2(0.5f, 0.5f));
    p = fma2(p, c, pk2(1.0f, 1.0f));
    p = fma2(p, c, pk2(1.0f, 1.0f));
    return p;
}

// tile smem layout: row-major 128 rows x 256B, 16B chunks XOR-swizzled by (row&7)
__device__ __forceinline__ void copy_tile_async(uint32_t dstb, int grow0, int tid) {
    #pragma unroll
    for (int l = 0; l < 8; l++) {
        int idx = tid + l * NTHR;              // 0..2047
        int row = idx >> 4;
        int ch  = idx & 15;
        cp_async16(dstb + row * 256 + ((ch ^ (row & 7)) << 4),
                   &g_xbf[(grow0 + row) * C_DIM + ch * 8]);
    }
}

// flat chunk index -> (it, jt0, njt): panel it, chunk q covers jt = it+2q, +1
__device__ __forceinline__ void job_decode(int f, int ntM, int& it, int& jt0, int& njt) {
    int i = 0;
    for (;;) {
        int pairs = (ntM - i + 1) >> 1;
        if (f < pairs) { it = i; jt0 = i + f * 2; njt = min(2, ntM - jt0); return; }
        f -= pairs; ++i;
    }
}

// ---------------- kernels ----------------
__global__ __launch_bounds__(512) void normalize_kernel(const float* __restrict__ x, int T) {
    int tid = blockIdx.x * 512 + threadIdx.x;
    if (tid < MAX_T) g_rowsum[tid] = 0.f;      // per-replay reset
    int row = tid >> 3;
    int sub = tid & 7;                         // 8 threads per row, 16 floats each
    if (row < T) {
        const float4* px = (const float4*)&x[row * C_DIM + sub * 16];
        float4 v0 = px[0], v1 = px[1], v2 = px[2], v3 = px[3];
        float s = v0.x*v0.x + v0.y*v0.y + v0.z*v0.z + v0.w*v0.w
                + v1.x*v1.x + v1.y*v1.y + v1.z*v1.z + v1.w*v1.w
                + v2.x*v2.x + v2.y*v2.y + v2.z*v2.z + v2.w*v2.w
                + v3.x*v3.x + v3.y*v3.y + v3.z*v3.z + v3.w*v3.w;
        #pragma unroll
        for (int o = 1; o < 8; o <<= 1) s += __shfl_xor_sync(0xffffffffu, s, o);
        float inv = 1.0f / fmaxf(sqrtf(s), 1e-8f);
        __nv_bfloat16* dst = &g_xbf[row * C_DIM + sub * 16];
        float4 vv[4] = {v0, v1, v2, v3};
        #pragma unroll
        for (int q = 0; q < 4; q++) {
            __nv_bfloat162 o0 = __floats2bfloat162_rn(vv[q].x * inv, vv[q].y * inv);
            __nv_bfloat162 o1 = __floats2bfloat162_rn(vv[q].z * inv, vv[q].w * inv);
            uint2 pk;
            pk.x = *(uint32_t*)&o0;
            pk.y = *(uint32_t*)&o1;
            *(uint2*)(dst + q * 4) = pk;
        }
    }
}

__global__ void __launch_bounds__(NTHR, 2) rowsum_tri(int T, int ntM) {
    extern __shared__ char smem[];
    const uint32_t sb = smem_u32(smem);
    const int tid  = threadIdx.x;
    const int wid  = tid >> 5;                 // 0..7
    const int lane = tid & 31;

    int it, jt0, njt;
    job_decode(blockIdx.x, ntM, it, jt0, njt);
    const int i0 = it * TM;

    // prefetch: group0 = {A, B0}; group1 = {B1}
    copy_tile_async(sb + OFF_A, i0, tid);
    copy_tile_async(sb + OFF_B0, jt0 * TM, tid);
    CP_COMMIT();
    if (njt == 2) {
        copy_tile_async(sb + OFF_B1, (jt0 + 1) * TM, tid);
        CP_COMMIT();
    }

    const int mq = wid >> 1;                   // M quarter: 32 rows
    const int nh = wid & 1;                    // N half: 64 cols of 128
    const int mrow = mq * 32;
    const int jloc = nh * 64;
    const int s7   = lane & 7;

    const int ro_a = (lane & 7) + ((lane >> 3) & 1) * 8;
    const int cg_a = (lane >> 4);
    const int ro_b = (lane & 7) + ((lane >> 4) & 1) * 8;
    const int cg_b = (lane >> 3) & 1;

    uint32_t a_addr[2];
    #pragma unroll
    for (int mi = 0; mi < 2; mi++)
        a_addr[mi] = sb + OFF_A + (mrow + mi * 16 + ro_a) * 256;

    for (int s = 0; s < njt; s++) {
        if (s == 0) { if (njt == 2) { CP_WAIT(1); } else { CP_WAIT(0); } }
        else        { CP_WAIT(0); }
        __syncthreads();

        const int jt  = jt0 + s;
        const int gj0 = jt * TM + jloc;
        const uint32_t bt = sb + (s ? OFF_B1 : OFF_B0);
        uint32_t b_addr[4];
        #pragma unroll
        for (int p = 0; p < 4; p++)
            b_addr[p] = bt + (jloc + p * 16 + ro_b) * 256;

        float c[2][8][4];
        #pragma unroll
        for (int mi = 0; mi < 2; mi++)
            #pragma unroll
            for (int ni = 0; ni < 8; ni++)
                #pragma unroll
                for (int q = 0; q < 4; q++) c[mi][ni][q] = 0.f;

        #pragma unroll
        for (int ks = 0; ks < 8; ks++) {
            const uint32_t chA = (uint32_t)(((ks * 2 + cg_a) ^ s7) << 4);
            const uint32_t chB = (uint32_t)(((ks * 2 + cg_b) ^ s7) << 4);
            uint32_t a[2][4], b[4][4];
            #pragma unroll
            for (int mi = 0; mi < 2; mi++) ldmatrix_x4(a[mi], a_addr[mi] + chA);
            #pragma unroll
            for (int p = 0; p < 4; p++)    ldmatrix_x4(b[p], b_addr[p] + chB);
            #pragma unroll
            for (int mi = 0; mi < 2; mi++)
                #pragma unroll
                for (int ni = 0; ni < 8; ni++)
                    mma_bf16(c[mi][ni], a[mi], &b[ni >> 1][(ni & 1) * 2]);
        }

        // ---- epilogue: exp once; row sums + (off-diag) col sums ----
        unsigned long long racc[4] = {0ull, 0ull, 0ull, 0ull};
        unsigned long long cacc[8] = {0ull,0ull,0ull,0ull,0ull,0ull,0ull,0ull};
        #pragma unroll
        for (int mi = 0; mi < 2; mi++)
            #pragma unroll
            for (int ni = 0; ni < 8; ni++) {
                unsigned long long e01 = exp_pk(pk2(c[mi][ni][0], c[mi][ni][1]));
                unsigned long long e23 = exp_pk(pk2(c[mi][ni][2], c[mi][ni][3]));
                racc[mi * 2]     = add2(racc[mi * 2], e01);
                racc[mi * 2 + 1] = add2(racc[mi * 2 + 1], e23);
                cacc[ni]         = add2(cacc[ni], add2(e01, e23));
            }

        // row sums: subtract padded (col >= T) contributions of this lane
        int padc = 0;
        if (gj0 + 64 > T) {
            #pragma unroll
            for (int ni = 0; ni < 8; ni++) {
                int col = gj0 + ni * 8 + 2 * (lane & 3);
                padc += (col >= T) + (col + 1 >= T);
            }
        }
        float rrow[4];
        #pragma unroll
        for (int q = 0; q < 4; q++) {
            float2 u = up2(racc[q]);
            rrow[q] = (u.x + u.y) - (float)padc;
            rrow[q] += __shfl_xor_sync(0xffffffffu, rrow[q], 1);
            rrow[q] += __shfl_xor_sync(0xffffffffu, rrow[q], 2);
        }
        if ((lane & 3) == 0) {
            int rbase = i0 + mrow + (lane >> 2);
            #pragma unroll
            for (int mi = 0; mi < 2; mi++)
                #pragma unroll
                for (int h = 0; h < 2; h++) {
                    int row = rbase + mi * 16 + h * 8;
                    if (row < T) atomicAdd(&g_rowsum[row], rrow[mi * 2 + h]);
                }
        }

        // col sums (symmetry) — skip the diagonal tile
        if (jt != it) {
            float padr = (float)min(32, max(0, i0 + mrow + 32 - T));
            #pragma unroll
            for (int ni = 0; ni < 8; ni++) {
                float2 u = up2(cacc[ni]);
                #pragma unroll
                for (int o = 4; o <= 16; o <<= 1) {
                    u.x += __shfl_xor_sync(0xffffffffu, u.x, o);
                    u.y += __shfl_xor_sync(0xffffffffu, u.y, o);
                }
                if (lane < 4) {
                    int col = gj0 + ni * 8 + 2 * lane;
                    if (col < T)     atomicAdd(&g_rowsum[col],     u.x - padr);
                    if (col + 1 < T) atomicAdd(&g_rowsum[col + 1], u.y - padr);
                }
            }
        }
    }
}

// warp-per-block: in-block cosines (fp32 dots over the same bf16 data) + loss
// terms; counter-fused final reduction writes out.
__global__ __launch_bounds__(256) void pairs_finalize(
    float rscale, int Bnum, int ncta, const int* __restrict__ kuai2,
    float* __restrict__ out)
{
    const int lane = threadIdx.x & 31;
    const int wid  = threadIdx.x >> 5;
    const int b    = blockIdx.x * 8 + wid;

    float warp_term = 0.f;
    if (b < Bnum) {
        float4 u[BLK];
        #pragma unroll
        for (int m = 0; m < BLK; m++) {
            const __nv_bfloat162* p =
                (const __nv_bfloat162*)&g_xbf[(b * BLK + m) * C_DIM + lane * 4];
            float2 lo = __bfloat1622float2(p[0]);
            float2 hi = __bfloat1622float2(p[1]);
            u[m] = make_float4(lo.x, lo.y, hi.x, hi.y);
        }
        float cm[BLK][BLK];
        #pragma unroll
        for (int i = 0; i < BLK; i++)
            #pragma unroll
            for (int j = i; j < BLK; j++) {
                float s = u[i].x * u[j].x + u[i].y * u[j].y
                        + u[i].z * u[j].z + u[i].w * u[j].w;
                #pragma unroll
                for (int o = 16; o > 0; o >>= 1) s += __shfl_xor_sync(0xffffffffu, s, o);
                cm[i][j] = s; cm[j][i] = s;
            }
        float term = 0.f;
        if (lane < BLK) {
            int i = lane;
            float es[BLK], bsum = 0.f;
            #pragma unroll
            for (int m = 0; m < BLK; m++) { es[m] = expf(cm[i][m]); bsum += es[m]; }
            float rs = g_rowsum[b * BLK + i];
            float negA = rscale * (rs - bsum);
            #pragma unroll
            for (int m = 0; m < BLK; m++)
                if (m != i) term += logf(es[m] + negA) - cm[i][m];
        }
        #pragma unroll
        for (int o = 16; o > 0; o >>= 1) term += __shfl_xor_sync(0xffffffffu, term, o);
        warp_term = term;
    }

    __shared__ float ws[8];
    __shared__ int s_fin;
    if (lane == 0) ws[wid] = warp_term;
    __syncthreads();
    if (threadIdx.x == 0) {
        float s = 0.f;
        #pragma unroll
        for (int k = 0; k < 8; k++) s += ws[k];
        g_pairpart[blockIdx.x] = s;
        __threadfence();
        int o = atomicAdd(&g_cnt, 1);
        s_fin = (o == ncta - 1);
        if (s_fin) g_cnt = 0;                  // reset for next replay
    }
    __syncthreads();
    if (s_fin && threadIdx.x < 32) {
        __threadfence();
        double s = 0.0;
        for (int i = threadIdx.x; i < ncta; i += 32) s += (double)g_pairpart[i];
        #pragma unroll
        for (int o = 16; o > 0; o >>= 1) s += __shfl_xor_sync(0xffffffffu, s, o);
        if (threadIdx.x == 0) {
            int k2 = *kuai2;
            out[0] = (float)(s / ((double)Bnum * (double)k2 * (double)(k2 - 1)));
        }
    }
}

// ---------------- launch ----------------
extern "C" void kernel_launch(void* const* d_in, const int* in_sizes, int n_in,
                              void* d_out, int out_size) {
    const float* x     = (const float*)d_in[0];
    const int*   kuai2 = (const int*)d_in[1];

    int T = in_sizes[0] / C_DIM;
    int B = T / BLK;
    float r = (float)(2 * B - 2) / (float)(T - BLK);
    int ntM = (T + TM - 1) / TM;

    int NJ = 0;
    for (int i = 0; i < ntM; i++) NJ += (ntM - i + 1) >> 1;   // chunk count
    int ncta_pairs = (B + 7) / 8;
    int nthr_norm = ((T * 8 > MAX_T) ? T * 8 : MAX_T);

    cudaFuncSetAttribute(rowsum_tri, cudaFuncAttributeMaxDynamicSharedMemorySize, SMEM_DYN);

    normalize_kernel<<<(nthr_norm + 511) / 512, 512>>>(x, T);
    rowsum_tri<<<NJ, NTHR, SMEM_DYN>>>(T, ntM);
    pairs_finalize<<<ncta_pairs, 256>>>(r, B, ncta_pairs, kuai2, (float*)d_out);
}